// round 16
// baseline (speedup 1.0000x reference)
#include <cuda_runtime.h>
#include <math.h>

#define N      4096
#define D      128
#define NW     128          // 4096 bits / 32
#define MLP_R  32           // rows per MLP block
#define XS2    68           // dup-x smem row stride (floats) = 2*32+4
#define CAP    192          // per-row unique-neighbor list capacity
#define GS     33           // padded stride for a 32-float group in smem
#define MEGA_B 512          // mega kernel blocks (all resident: 148*4=592)
#define HLP_B  128          // helper blocks in kernel 1
#define INV232 2.3283064365386963e-10f   // 2^-32

// ---------------- scratch (device globals) ----------------------------------
__device__ unsigned       g_A  [N * NW];
__device__ unsigned       g_A2 [N * NW];
__device__ unsigned short g_nbr[N * CAP];   // unique neighbor lists
__device__ int            g_cnt[N];
__device__ float          g_Wt [3 * D * D]; // pre-transposed weights, k-major
__device__ float          g_a0[N];
__device__ float          g_av2[N];
__device__ long long      g_stepq[N];
__device__ float          g_step[N];
__device__ int            g_is64;
__device__ unsigned       g_tick[4];        // monotone ticket-barrier counters

#define FMA2(acc, w, x) asm("fma.rn.f32x2 %0, %1, %2, %0;" : "+l"(acc) : "l"(w), "l"(x))
union U64F2 { unsigned long long u; float2 f; };

// ---------------- replay-safe ticket barrier (cohort must be co-resident) ---
__device__ __forceinline__ void ticket_barrier(unsigned* cnt, unsigned cohort) {
    __syncthreads();
    if (threadIdx.x == 0) {
        __threadfence();                              // release (cumulative)
        unsigned t = atomicAdd(cnt, 1u);
        unsigned target = (t / cohort + 1u) * cohort; // my cohort's finish line
        unsigned v;
        do {
            asm volatile("ld.acquire.gpu.global.u32 %0, [%1];"
                         : "=r"(v) : "l"(cnt));
        } while (v < target);
    }
    __syncthreads();
}

// ---------------- kernel 1: MLP blocks (0..127) || helper blocks (128..255) --
// MLP: 32 rows/block, thread tile 4 rows x 8 cols (16 FMA2/k) -> 2B/FMA.
// Helpers: zero A/stepq/cnt (+detect) -> barrier -> bitset + nbr-list build.
__global__ __launch_bounds__(128, 2)
void mlp_mega_kernel(const float* __restrict__ coeffs,
                     const float* __restrict__ W0,
                     const float* __restrict__ b0,
                     const float* __restrict__ W1,
                     const float* __restrict__ W2,
                     const float* __restrict__ W3,
                     const float* __restrict__ b3,
                     const void* __restrict__ ei, int ne) {
    __shared__ float xa[128 * XS2];
    __shared__ float xb[128 * XS2];

    const int b   = blockIdx.x;
    const int tid = threadIdx.x;

    if (b >= 128) {
        // ================= helper path ======================================
        const int hb  = b - 128;
        const int idx = hb * 128 + tid;            // 0..16383
        const uint4 z = make_uint4(0u, 0u, 0u, 0u);
        uint4* pA = (uint4*)g_A;
        #pragma unroll
        for (int q = 0; q < 8; q++) pA[idx + q * 16384] = z;
        if (idx < 2048) ((uint4*)g_stepq)[idx] = z;
        if (idx < 1024) ((uint4*)g_cnt)[idx]   = z;

        if (hb == 0) {                              // dtype detection
            __shared__ int bad;
            if (tid == 0) bad = 0;
            __syncthreads();
            const long long* p = (const long long*)ei;
            for (int i = tid; i < 2048; i += 128) {
                long long v = p[i];
                if (v < 0 || v >= N) bad = 1;
            }
            __syncthreads();
            if (tid == 0) g_is64 = bad ? 0 : 1;
        }

        ticket_barrier(&g_tick[1], HLP_B);

        // edge bitset + unique neighbor lists (no a0 dependency)
        const int is64 = g_is64;
        for (int e = idx; e < ne; e += HLP_B * 128) {
            int row, col;
            if (is64) {
                const long long* p = (const long long*)ei;
                row = (int)p[e];
                col = (int)p[ne + e];
            } else {
                const int* p = (const int*)ei;
                row = p[e];
                col = p[ne + e];
            }
            unsigned bit = 1u << (col & 31);
            unsigned old = atomicOr(&g_A[row * NW + (col >> 5)], bit);
            if (!(old & bit)) {
                int pp = atomicAdd(&g_cnt[row], 1);
                if (pp < CAP) g_nbr[row * CAP + pp] = (unsigned short)col;
            }
        }
        return;
    }

    // ================= MLP path =============================================
    if (b < 48) {   // transpose one 32x32 tile of W0..W2 into g_Wt (k-major)
        float (*tile)[33] = (float(*)[33])xa;       // alias smem
        const int m = b >> 4;
        const int t = b & 15;
        const int I = t >> 2;                       // c-tile
        const int J = t & 3;                        // k-tile
        const int tx = tid & 31;
        const int ty = tid >> 5;                    // 0..3
        const float* W = (m == 0) ? W0 : (m == 1 ? W1 : W2);
        #pragma unroll
        for (int rr = 0; rr < 8; rr++) {
            int row = ty + rr * 4;
            tile[row][tx] = W[(I * 32 + row) * 128 + J * 32 + tx];
        }
        __syncthreads();
        #pragma unroll
        for (int rr = 0; rr < 8; rr++) {
            int row = ty + rr * 4;
            g_Wt[m * 16384 + (J * 32 + row) * 128 + I * 32 + tx] = tile[tx][row];
        }
        __syncthreads();
    }

    ticket_barrier(&g_tick[0], 128);

    const int r0 = b * MLP_R;
    const int rg = tid >> 4;     // 8 row-groups of 4 rows
    const int cg = tid & 15;     // 16 col-groups of 8 cols (pairs cg*2+32j)

    // stage coeffs dup-transposed: xa[k*XS2 + 2r] = {x,x}
    #pragma unroll
    for (int it = 0; it < 8; it++) {
        int idx = it * 128 + tid;                  // 0..1023
        int r  = idx >> 5;                         // 0..31
        int kq = idx & 31;                         // 0..31 (float4 index)
        float4 v = *(const float4*)&coeffs[(r0 + r) * 128 + kq * 4];
        float vv[4] = {v.x, v.y, v.z, v.w};
        #pragma unroll
        for (int q = 0; q < 4; q++)
            *(float2*)&xa[(kq * 4 + q) * XS2 + 2 * r] = make_float2(vv[q], vv[q]);
    }
    __syncthreads();

    float* Xin  = xa;
    float* Xout = xb;

    #pragma unroll
    for (int layer = 0; layer < 3; layer++) {
        const float* Wl = g_Wt + layer * 16384;

        unsigned long long acc[4][4];
        #pragma unroll
        for (int r = 0; r < 4; r++)
            #pragma unroll
            for (int j = 0; j < 4; j++) acc[r][j] = 0ull;

        #pragma unroll 4
        for (int k = 0; k < 128; k++) {
            const float* xp = Xin + k * XS2 + rg * 8;
            ulonglong2 x01 = *(const ulonglong2*)(xp);       // rows 0,1 dup
            ulonglong2 x23 = *(const ulonglong2*)(xp + 4);   // rows 2,3 dup
            const float* wrow = Wl + k * 128 + cg * 2;
            unsigned long long w0 = *(const unsigned long long*)(wrow);
            unsigned long long w1 = *(const unsigned long long*)(wrow + 32);
            unsigned long long w2 = *(const unsigned long long*)(wrow + 64);
            unsigned long long w3 = *(const unsigned long long*)(wrow + 96);
            FMA2(acc[0][0], w0, x01.x); FMA2(acc[0][1], w1, x01.x);
            FMA2(acc[0][2], w2, x01.x); FMA2(acc[0][3], w3, x01.x);
            FMA2(acc[1][0], w0, x01.y); FMA2(acc[1][1], w1, x01.y);
            FMA2(acc[1][2], w2, x01.y); FMA2(acc[1][3], w3, x01.y);
            FMA2(acc[2][0], w0, x23.x); FMA2(acc[2][1], w1, x23.x);
            FMA2(acc[2][2], w2, x23.x); FMA2(acc[2][3], w3, x23.x);
            FMA2(acc[3][0], w0, x23.y); FMA2(acc[3][1], w1, x23.y);
            FMA2(acc[3][2], w2, x23.y); FMA2(acc[3][3], w3, x23.y);
        }

        float o[4][8];
        #pragma unroll
        for (int r = 0; r < 4; r++)
            #pragma unroll
            for (int j = 0; j < 4; j++) {
                U64F2 u; u.u = acc[r][j];
                o[r][2 * j] = u.f.x; o[r][2 * j + 1] = u.f.y;
            }
        if (layer == 0) {
            #pragma unroll
            for (int j = 0; j < 4; j++) {
                float2 bb = *(const float2*)&b0[32 * j + cg * 2];
                #pragma unroll
                for (int r = 0; r < 4; r++) {
                    o[r][2 * j] += bb.x; o[r][2 * j + 1] += bb.y;
                }
            }
        }
        #pragma unroll
        for (int r = 0; r < 4; r++)
            #pragma unroll
            for (int c = 0; c < 8; c++) o[r][c] = fmaxf(o[r][c], 0.f);

        if (layer < 2) {
            #pragma unroll
            for (int r = 0; r < 4; r++) {
                int row = rg * 4 + r;
                #pragma unroll
                for (int j = 0; j < 4; j++) {
                    int k0 = cg * 2 + 32 * j;
                    *(float2*)&Xout[(k0    ) * XS2 + 2 * row] =
                        make_float2(o[r][2*j],   o[r][2*j]);
                    *(float2*)&Xout[(k0 + 1) * XS2 + 2 * row] =
                        make_float2(o[r][2*j+1], o[r][2*j+1]);
                }
            }
            __syncthreads();
            float* tmp = Xin; Xin = Xout; Xout = tmp;
        } else {
            float p[4] = {0.f, 0.f, 0.f, 0.f};
            #pragma unroll
            for (int j = 0; j < 4; j++) {
                float2 w3v = *(const float2*)&W3[32 * j + cg * 2];
                #pragma unroll
                for (int r = 0; r < 4; r++)
                    p[r] = fmaf(o[r][2*j], w3v.x, fmaf(o[r][2*j+1], w3v.y, p[r]));
            }
            #pragma unroll
            for (int off = 8; off; off >>= 1)
                #pragma unroll
                for (int r = 0; r < 4; r++)
                    p[r] += __shfl_down_sync(0xffffffffu, p[r], off, 16);
            if (cg == 0) {
                float bb = b3[0];
                #pragma unroll
                for (int r = 0; r < 4; r++)
                    g_a0[r0 + rg * 4 + r] = p[r] + bb;
            }
        }
    }
}

// ---------------- hop body (shared by both phases) ----------------------------
__device__ __forceinline__ void hop_body(int phase, float* __restrict__ out_final,
                                         float* vsh, float* seg, float* part,
                                         int blk) {
    const unsigned* M = phase ? g_A2 : g_A;

    const int tid  = threadIdx.x;
    const int wid  = tid >> 5;
    const int lane = tid & 31;
    const int r    = wid >> 1;          // row within block (0..7)
    const int h    = wid & 1;           // column half (0..1)
    const int i    = blk * 8 + r;

    // ---- 1. OR over neighbor rows via unique neighbor list ------------------
    const int woff = h * 64 + 2 * lane;              // this lane's word pair
    const int cnt  = g_cnt[i];
    unsigned ax = 0u, ay = 0u;

    if (cnt <= CAP) {
        const unsigned short* nb = g_nbr + i * CAP;
        int j = 0;
        for (; j + 8 <= cnt; j += 8) {
            uint4 nn = *(const uint4*)&nb[j];        // 8 ushorts, uniform
            int n0 = nn.x & 0xffff, n1 = nn.x >> 16;
            int n2 = nn.y & 0xffff, n3 = nn.y >> 16;
            int n4 = nn.z & 0xffff, n5 = nn.z >> 16;
            int n6 = nn.w & 0xffff, n7 = nn.w >> 16;
            uint2 q0 = __ldg((const uint2*)&M[n0 * NW + woff]);
            uint2 q1 = __ldg((const uint2*)&M[n1 * NW + woff]);
            uint2 q2 = __ldg((const uint2*)&M[n2 * NW + woff]);
            uint2 q3 = __ldg((const uint2*)&M[n3 * NW + woff]);
            uint2 q4 = __ldg((const uint2*)&M[n4 * NW + woff]);
            uint2 q5 = __ldg((const uint2*)&M[n5 * NW + woff]);
            uint2 q6 = __ldg((const uint2*)&M[n6 * NW + woff]);
            uint2 q7 = __ldg((const uint2*)&M[n7 * NW + woff]);
            ax |= ((q0.x | q1.x) | (q2.x | q3.x)) | ((q4.x | q5.x) | (q6.x | q7.x));
            ay |= ((q0.y | q1.y) | (q2.y | q3.y)) | ((q4.y | q5.y) | (q6.y | q7.y));
        }
        for (; j < cnt; j++) {
            int n = nb[j];
            uint2 q = __ldg((const uint2*)&M[n * NW + woff]);
            ax |= q.x; ay |= q.y;
        }
    } else {
        // fallback: bit-walk over the adjacency row (pathological degrees)
        const uint4* Arow = (const uint4*)&g_A[i * NW];
        for (int c = 0; c < 32; c++) {
            uint4 mw = __ldg(&Arow[c]);
            int jb = c * 128;
            unsigned m;
            m = mw.x; while (m) { int b = __ffs((int)m) - 1; m &= m - 1;
                uint2 q = *(const uint2*)&M[(jb + b) * NW + woff]; ax |= q.x; ay |= q.y; }
            m = mw.y; while (m) { int b = __ffs((int)m) - 1; m &= m - 1;
                uint2 q = *(const uint2*)&M[(jb + 32 + b) * NW + woff]; ax |= q.x; ay |= q.y; }
            m = mw.z; while (m) { int b = __ffs((int)m) - 1; m &= m - 1;
                uint2 q = *(const uint2*)&M[(jb + 64 + b) * NW + woff]; ax |= q.x; ay |= q.y; }
            m = mw.w; while (m) { int b = __ffs((int)m) - 1; m &= m - 1;
                uint2 q = *(const uint2*)&M[(jb + 96 + b) * NW + woff]; ax |= q.x; ay |= q.y; }
        }
    }

    if (!phase) *(uint2*)&g_A2[i * NW + woff] = make_uint2(ax, ay);

    // ---- 2. load angle vector, store to padded smem + per-group sums -------
    {
        float vv[8];
        if (phase) {
            float4 u0 = *(const float4*)&g_av2[tid * 8];
            float4 u1 = *(const float4*)&g_av2[tid * 8 + 4];
            vv[0]=u0.x; vv[1]=u0.y; vv[2]=u0.z; vv[3]=u0.w;
            vv[4]=u1.x; vv[5]=u1.y; vv[6]=u1.z; vv[7]=u1.w;
        } else {
            float4 u0 = *(const float4*)&g_a0[tid * 8];
            float4 u1 = *(const float4*)&g_a0[tid * 8 + 4];
            const longlong2* sq = (const longlong2*)g_stepq + tid * 4;
            longlong2 q0 = sq[0], q1 = sq[1], q2 = sq[2], q3 = sq[3];
            vv[0] = u0.x + __ll2float_rn(q0.x) * INV232;
            vv[1] = u0.y + __ll2float_rn(q0.y) * INV232;
            vv[2] = u0.z + __ll2float_rn(q1.x) * INV232;
            vv[3] = u0.w + __ll2float_rn(q1.y) * INV232;
            vv[4] = u1.x + __ll2float_rn(q2.x) * INV232;
            vv[5] = u1.y + __ll2float_rn(q2.y) * INV232;
            vv[6] = u1.z + __ll2float_rn(q3.x) * INV232;
            vv[7] = u1.w + __ll2float_rn(q3.y) * INV232;
        }
        const int g  = tid >> 2;            // 32-float group (one per 4 threads)
        const int o0 = (tid & 3) * 8;       // offset within group
        float s = 0.f;
        #pragma unroll
        for (int q = 0; q < 8; q++) {
            vsh[g * GS + o0 + q] = vv[q];
            s += vv[q];
        }
        s += __shfl_down_sync(0xffffffffu, s, 2, 4);
        s += __shfl_down_sync(0xffffffffu, s, 1, 4);
        if ((tid & 3) == 0) seg[g] = s;
    }
    __syncthreads();

    // ---- 3. gated sum over this lane's two 32-float groups ------------------
    const float* base0 = vsh + woff * GS;          // group woff
    const float* base1 = vsh + (woff + 1) * GS;    // group woff+1
    int pc = __popc(ax) + __popc(ay);
    float sv;
    if (pc > 32) {
        sv = seg[woff] + seg[woff + 1];
        unsigned m;
        m = ~ax; while (m) { int b = __ffs((int)m) - 1; m &= m - 1; sv -= base0[b]; }
        m = ~ay; while (m) { int b = __ffs((int)m) - 1; m &= m - 1; sv -= base1[b]; }
    } else {
        sv = 0.f;
        unsigned m;
        m = ax; while (m) { int b = __ffs((int)m) - 1; m &= m - 1; sv += base0[b]; }
        m = ay; while (m) { int b = __ffs((int)m) - 1; m &= m - 1; sv += base1[b]; }
    }
    #pragma unroll
    for (int o = 16; o; o >>= 1) sv += __shfl_down_sync(0xffffffffu, sv, o);
    if (lane == 0) part[wid] = sv;
    __syncthreads();

    // ---- 4. combine halves + epilogue (threads 0..7 handle rows 0..7) ------
    if (tid < 8) {
        const int ii = blk * 8 + tid;
        float vi = vsh[(ii >> 5) * GS + (ii & 31)];
        float tot = part[2 * tid] + part[2 * tid + 1];
        if (!phase) {
            float s1 = __ll2float_rn(g_stepq[ii]) * INV232;
            float ns = s1 + 1.0986122886681098f * tot;            // ln 3
            g_step[ii] = ns;
            g_av2[ii]  = vi + ns;                                  // a1 + step
        } else {
            out_final[ii] = vi + g_step[ii] + 1.3862943611198906f * tot; // ln 4
        }
    }
}

// ---------------- mega: stepq scatter + barrier + hop0 + barrier + hop1 ------
__global__ __launch_bounds__(512, 4)
void mega_kernel(const void* __restrict__ ei, int ne, float* __restrict__ out) {
    __shared__ float vsh[128 * GS];
    __shared__ float seg[128];
    __shared__ float part[16];

    // ---- hop-1 scatter only (bitset + nbr lists built in kernel 1) ---------
    const int is64   = g_is64;
    const int stride = gridDim.x * blockDim.x;
    for (int e = blockIdx.x * blockDim.x + threadIdx.x; e < ne; e += stride) {
        int row, col;
        if (is64) {
            const long long* p = (const long long*)ei;
            row = (int)p[e];
            col = (int)p[ne + e];
        } else {
            const int* p = (const int*)ei;
            row = p[e];
            col = p[ne + e];
        }
        float v = 0.69314718055994531f * g_a0[col];
        long long q = __float2ll_rn(v * 4294967296.0f);
        atomicAdd((unsigned long long*)&g_stepq[row], (unsigned long long)q);
    }

    ticket_barrier(&g_tick[2], MEGA_B);
    hop_body(0, out, vsh, seg, part, blockIdx.x);
    ticket_barrier(&g_tick[3], MEGA_B);
    hop_body(1, out, vsh, seg, part, blockIdx.x);
}

// ---------------- launch ----------------------------------------------------
extern "C" void kernel_launch(void* const* d_in, const int* in_sizes, int n_in,
                              void* d_out, int out_size) {
    const float* coeffs = (const float*)d_in[0];
    const void*  ei     = d_in[1];
    const float* W0     = (const float*)d_in[2];
    const float* b0     = (const float*)d_in[3];
    const float* W1     = (const float*)d_in[4];
    const float* W2     = (const float*)d_in[5];
    const float* W3     = (const float*)d_in[6];
    const float* b3     = (const float*)d_in[7];
    float* out = (float*)d_out;

    const int ne = in_sizes[1] / 2;

    mlp_mega_kernel<<<128 + HLP_B, 128>>>(coeffs, W0, b0, W1, W2, W3, b3, ei, ne);

    mega_kernel<<<MEGA_B, 512>>>(ei, ne, out);
}

// round 17
// speedup vs baseline: 1.2718x; 1.2718x over previous
#include <cuda_runtime.h>
#include <math.h>

#define N      4096
#define D      128
#define NW     128          // 4096 bits / 32
#define MLP_R  16           // rows per MLP block
#define XS     132          // x smem row stride (floats), 528B = 16B-aligned
#define CAP    192          // per-row unique-neighbor list capacity
#define GS     33           // padded stride for a 32-float group in smem
#define MEGA_B 512          // mega kernel blocks (all resident: 148*4=592)
#define HLP_B  128          // helper blocks in kernel 1
#define INV232 2.3283064365386963e-10f   // 2^-32

// ---------------- scratch (device globals) ----------------------------------
__device__ unsigned       g_A  [N * NW];
__device__ unsigned       g_A2 [N * NW];
__device__ unsigned short g_nbr[N * CAP];   // unique neighbor lists
__device__ int            g_cnt[N];
__device__ float          g_Wt [3 * D * D]; // k-pair-packed weights Wp[kp][c*2+par]
__device__ float          g_a0[N];
__device__ float          g_av2[N];
__device__ long long      g_stepq[N];
__device__ float          g_step[N];
__device__ int            g_is64;
__device__ unsigned       g_tick[4];        // monotone ticket-barrier counters

#define FMA2(acc, w, x) asm("fma.rn.f32x2 %0, %1, %2, %0;" : "+l"(acc) : "l"(w), "l"(x))
union U64F2 { unsigned long long u; float2 f; };

// ---------------- replay-safe ticket barrier (cohort must be co-resident) ---
__device__ __forceinline__ void ticket_barrier(unsigned* cnt, unsigned cohort) {
    __syncthreads();
    if (threadIdx.x == 0) {
        __threadfence();                              // release (cumulative)
        unsigned t = atomicAdd(cnt, 1u);
        unsigned target = (t / cohort + 1u) * cohort; // my cohort's finish line
        unsigned v;
        do {
            asm volatile("ld.acquire.gpu.global.u32 %0, [%1];"
                         : "=r"(v) : "l"(cnt));
        } while (v < target);
    }
    __syncthreads();
}

// ---------------- kernel 1: MLP blocks (0..255) || helper blocks (256..383) --
// MLP: 16 rows/block, thread tile 4 rows x 4 cols, k-pair FMA2 (no x dup).
// Helpers: zero A/stepq/cnt (+detect) -> barrier -> bitset + nbr-list build.
__global__ __launch_bounds__(128, 3)
void mlp_mega_kernel(const float* __restrict__ coeffs,
                     const float* __restrict__ W0,
                     const float* __restrict__ b0,
                     const float* __restrict__ W1,
                     const float* __restrict__ W2,
                     const float* __restrict__ W3,
                     const float* __restrict__ b3,
                     const void* __restrict__ ei, int ne) {
    __shared__ float xa[MLP_R * XS];
    __shared__ float xb[MLP_R * XS];

    const int b   = blockIdx.x;
    const int tid = threadIdx.x;

    if (b >= 256) {
        // ================= helper path ======================================
        const int hb  = b - 256;
        const int idx = hb * 128 + tid;            // 0..16383
        const uint4 z = make_uint4(0u, 0u, 0u, 0u);
        uint4* pA = (uint4*)g_A;
        #pragma unroll
        for (int q = 0; q < 8; q++) pA[idx + q * 16384] = z;
        if (idx < 2048) ((uint4*)g_stepq)[idx] = z;
        if (idx < 1024) ((uint4*)g_cnt)[idx]   = z;

        if (hb == 0) {                              // dtype detection
            __shared__ int bad;
            if (tid == 0) bad = 0;
            __syncthreads();
            const long long* p = (const long long*)ei;
            for (int i = tid; i < 2048; i += 128) {
                long long v = p[i];
                if (v < 0 || v >= N) bad = 1;
            }
            __syncthreads();
            if (tid == 0) g_is64 = bad ? 0 : 1;
        }

        ticket_barrier(&g_tick[1], HLP_B);

        // edge bitset + unique neighbor lists (no a0 dependency)
        const int is64 = g_is64;
        for (int e = idx; e < ne; e += HLP_B * 128) {
            int row, col;
            if (is64) {
                const long long* p = (const long long*)ei;
                row = (int)p[e];
                col = (int)p[ne + e];
            } else {
                const int* p = (const int*)ei;
                row = p[e];
                col = p[ne + e];
            }
            unsigned bit = 1u << (col & 31);
            unsigned old = atomicOr(&g_A[row * NW + (col >> 5)], bit);
            if (!(old & bit)) {
                int pp = atomicAdd(&g_cnt[row], 1);
                if (pp < CAP) g_nbr[row * CAP + pp] = (unsigned short)col;
            }
        }
        return;
    }

    // ================= MLP path =============================================
    if (b < 48) {   // pack one 32x32 tile of W0..W2 into Wp[kp][c*2+par]
        float (*tile)[33] = (float(*)[33])xa;       // alias smem
        const int m = b >> 4;
        const int t = b & 15;
        const int I = t >> 2;                       // c-tile
        const int J = t & 3;                        // k-tile
        const int tx = tid & 31;
        const int ty = tid >> 5;                    // 0..3
        const float* W = (m == 0) ? W0 : (m == 1 ? W1 : W2);
        #pragma unroll
        for (int rr = 0; rr < 8; rr++) {
            int row = ty + rr * 4;                  // c within tile
            tile[row][tx] = W[(I * 32 + row) * 128 + J * 32 + tx];
        }
        __syncthreads();
        // write: Wp[(J*16+kpl)*256 + (I*32+c)*2 + par] = W[c][J*32+2*kpl+par]
        #pragma unroll
        for (int q = 0; q < 4; q++) {
            int kpl = ty + q * 4;                   // 0..15
            float2 v = make_float2(tile[tx][2 * kpl], tile[tx][2 * kpl + 1]);
            *(float2*)&g_Wt[m * 16384 + (J * 16 + kpl) * 256 + (I * 32 + tx) * 2] = v;
        }
        __syncthreads();
    }

    ticket_barrier(&g_tick[0], 256);

    const int r0 = b * MLP_R;
    const int rq = tid >> 5;     // 4 row-groups of 4 rows (= warp id)
    const int cq = tid & 31;     // 32 col-groups of 4 cols

    // stage coeffs row-major (straight copy)
    #pragma unroll
    for (int it = 0; it < 4; it++) {
        int idx = it * 128 + tid;                  // 0..511
        int r  = idx >> 5;                         // 0..15
        int k4 = idx & 31;
        *(float4*)&xa[r * XS + k4 * 4] = *(const float4*)&coeffs[(r0 + r) * 128 + k4 * 4];
    }
    __syncthreads();

    float* Xin  = xa;
    float* Xout = xb;

    #pragma unroll
    for (int layer = 0; layer < 3; layer++) {
        const float* Wl = g_Wt + layer * 16384;

        unsigned long long acc[4][4];
        #pragma unroll
        for (int r = 0; r < 4; r++)
            #pragma unroll
            for (int c = 0; c < 4; c++) acc[r][c] = 0ull;

        const float* x0 = Xin + (rq * 4) * XS;

        #pragma unroll 4
        for (int kp2 = 0; kp2 < 32; kp2++) {       // 4 k per iteration
            ulonglong2 xr0 = *(const ulonglong2*)(x0 + kp2 * 4);
            ulonglong2 xr1 = *(const ulonglong2*)(x0 + XS + kp2 * 4);
            ulonglong2 xr2 = *(const ulonglong2*)(x0 + 2 * XS + kp2 * 4);
            ulonglong2 xr3 = *(const ulonglong2*)(x0 + 3 * XS + kp2 * 4);
            const float* wp = Wl + kp2 * 512 + cq * 8;
            ulonglong2 wa0 = *(const ulonglong2*)(wp);         // kpair0: c0,c1
            ulonglong2 wa1 = *(const ulonglong2*)(wp + 4);     // kpair0: c2,c3
            ulonglong2 wb0 = *(const ulonglong2*)(wp + 256);   // kpair1: c0,c1
            ulonglong2 wb1 = *(const ulonglong2*)(wp + 260);   // kpair1: c2,c3
            FMA2(acc[0][0], wa0.x, xr0.x); FMA2(acc[0][0], wb0.x, xr0.y);
            FMA2(acc[0][1], wa0.y, xr0.x); FMA2(acc[0][1], wb0.y, xr0.y);
            FMA2(acc[0][2], wa1.x, xr0.x); FMA2(acc[0][2], wb1.x, xr0.y);
            FMA2(acc[0][3], wa1.y, xr0.x); FMA2(acc[0][3], wb1.y, xr0.y);
            FMA2(acc[1][0], wa0.x, xr1.x); FMA2(acc[1][0], wb0.x, xr1.y);
            FMA2(acc[1][1], wa0.y, xr1.x); FMA2(acc[1][1], wb0.y, xr1.y);
            FMA2(acc[1][2], wa1.x, xr1.x); FMA2(acc[1][2], wb1.x, xr1.y);
            FMA2(acc[1][3], wa1.y, xr1.x); FMA2(acc[1][3], wb1.y, xr1.y);
            FMA2(acc[2][0], wa0.x, xr2.x); FMA2(acc[2][0], wb0.x, xr2.y);
            FMA2(acc[2][1], wa0.y, xr2.x); FMA2(acc[2][1], wb0.y, xr2.y);
            FMA2(acc[2][2], wa1.x, xr2.x); FMA2(acc[2][2], wb1.x, xr2.y);
            FMA2(acc[2][3], wa1.y, xr2.x); FMA2(acc[2][3], wb1.y, xr2.y);
            FMA2(acc[3][0], wa0.x, xr3.x); FMA2(acc[3][0], wb0.x, xr3.y);
            FMA2(acc[3][1], wa0.y, xr3.x); FMA2(acc[3][1], wb0.y, xr3.y);
            FMA2(acc[3][2], wa1.x, xr3.x); FMA2(acc[3][2], wb1.x, xr3.y);
            FMA2(acc[3][3], wa1.y, xr3.x); FMA2(acc[3][3], wb1.y, xr3.y);
        }

        float o[4][4];
        #pragma unroll
        for (int r = 0; r < 4; r++)
            #pragma unroll
            for (int c = 0; c < 4; c++) {
                U64F2 u; u.u = acc[r][c];
                o[r][c] = u.f.x + u.f.y;           // even-k + odd-k partials
            }
        if (layer == 0) {
            float4 bb = *(const float4*)&b0[cq * 4];
            #pragma unroll
            for (int r = 0; r < 4; r++) {
                o[r][0] += bb.x; o[r][1] += bb.y;
                o[r][2] += bb.z; o[r][3] += bb.w;
            }
        }
        #pragma unroll
        for (int r = 0; r < 4; r++)
            #pragma unroll
            for (int c = 0; c < 4; c++) o[r][c] = fmaxf(o[r][c], 0.f);

        if (layer < 2) {
            #pragma unroll
            for (int r = 0; r < 4; r++) {
                int row = rq * 4 + r;
                *(float4*)&Xout[row * XS + cq * 4] =
                    make_float4(o[r][0], o[r][1], o[r][2], o[r][3]);
            }
            __syncthreads();
            float* tmp = Xin; Xin = Xout; Xout = tmp;
        } else {
            float4 w3v = *(const float4*)&W3[cq * 4];
            float p[4];
            #pragma unroll
            for (int r = 0; r < 4; r++) {
                p[r] = o[r][0] * w3v.x + o[r][1] * w3v.y
                     + o[r][2] * w3v.z + o[r][3] * w3v.w;
                #pragma unroll
                for (int off = 16; off; off >>= 1)
                    p[r] += __shfl_down_sync(0xffffffffu, p[r], off);
            }
            if (cq == 0) {
                float bb = b3[0];
                #pragma unroll
                for (int r = 0; r < 4; r++)
                    g_a0[r0 + rq * 4 + r] = p[r] + bb;
            }
        }
    }
}

// ---------------- hop body (shared by both phases) ----------------------------
__device__ __forceinline__ void hop_body(int phase, float* __restrict__ out_final,
                                         float* vsh, float* seg, float* part,
                                         int blk) {
    const unsigned* M = phase ? g_A2 : g_A;

    const int tid  = threadIdx.x;
    const int wid  = tid >> 5;
    const int lane = tid & 31;
    const int r    = wid >> 1;          // row within block (0..7)
    const int h    = wid & 1;           // column half (0..1)
    const int i    = blk * 8 + r;

    // ---- 1. OR over neighbor rows via unique neighbor list ------------------
    const int woff = h * 64 + 2 * lane;              // this lane's word pair
    const int cnt  = g_cnt[i];
    unsigned ax = 0u, ay = 0u;

    if (cnt <= CAP) {
        const unsigned short* nb = g_nbr + i * CAP;
        int j = 0;
        for (; j + 8 <= cnt; j += 8) {
            uint4 nn = *(const uint4*)&nb[j];        // 8 ushorts, uniform
            int n0 = nn.x & 0xffff, n1 = nn.x >> 16;
            int n2 = nn.y & 0xffff, n3 = nn.y >> 16;
            int n4 = nn.z & 0xffff, n5 = nn.z >> 16;
            int n6 = nn.w & 0xffff, n7 = nn.w >> 16;
            uint2 q0 = __ldg((const uint2*)&M[n0 * NW + woff]);
            uint2 q1 = __ldg((const uint2*)&M[n1 * NW + woff]);
            uint2 q2 = __ldg((const uint2*)&M[n2 * NW + woff]);
            uint2 q3 = __ldg((const uint2*)&M[n3 * NW + woff]);
            uint2 q4 = __ldg((const uint2*)&M[n4 * NW + woff]);
            uint2 q5 = __ldg((const uint2*)&M[n5 * NW + woff]);
            uint2 q6 = __ldg((const uint2*)&M[n6 * NW + woff]);
            uint2 q7 = __ldg((const uint2*)&M[n7 * NW + woff]);
            ax |= ((q0.x | q1.x) | (q2.x | q3.x)) | ((q4.x | q5.x) | (q6.x | q7.x));
            ay |= ((q0.y | q1.y) | (q2.y | q3.y)) | ((q4.y | q5.y) | (q6.y | q7.y));
        }
        for (; j < cnt; j++) {
            int n = nb[j];
            uint2 q = __ldg((const uint2*)&M[n * NW + woff]);
            ax |= q.x; ay |= q.y;
        }
    } else {
        // fallback: bit-walk over the adjacency row (pathological degrees)
        const uint4* Arow = (const uint4*)&g_A[i * NW];
        for (int c = 0; c < 32; c++) {
            uint4 mw = __ldg(&Arow[c]);
            int jb = c * 128;
            unsigned m;
            m = mw.x; while (m) { int b = __ffs((int)m) - 1; m &= m - 1;
                uint2 q = *(const uint2*)&M[(jb + b) * NW + woff]; ax |= q.x; ay |= q.y; }
            m = mw.y; while (m) { int b = __ffs((int)m) - 1; m &= m - 1;
                uint2 q = *(const uint2*)&M[(jb + 32 + b) * NW + woff]; ax |= q.x; ay |= q.y; }
            m = mw.z; while (m) { int b = __ffs((int)m) - 1; m &= m - 1;
                uint2 q = *(const uint2*)&M[(jb + 64 + b) * NW + woff]; ax |= q.x; ay |= q.y; }
            m = mw.w; while (m) { int b = __ffs((int)m) - 1; m &= m - 1;
                uint2 q = *(const uint2*)&M[(jb + 96 + b) * NW + woff]; ax |= q.x; ay |= q.y; }
        }
    }

    if (!phase) *(uint2*)&g_A2[i * NW + woff] = make_uint2(ax, ay);

    // ---- 2. load angle vector, store to padded smem + per-group sums -------
    {
        float vv[8];
        if (phase) {
            float4 u0 = *(const float4*)&g_av2[tid * 8];
            float4 u1 = *(const float4*)&g_av2[tid * 8 + 4];
            vv[0]=u0.x; vv[1]=u0.y; vv[2]=u0.z; vv[3]=u0.w;
            vv[4]=u1.x; vv[5]=u1.y; vv[6]=u1.z; vv[7]=u1.w;
        } else {
            float4 u0 = *(const float4*)&g_a0[tid * 8];
            float4 u1 = *(const float4*)&g_a0[tid * 8 + 4];
            const longlong2* sq = (const longlong2*)g_stepq + tid * 4;
            longlong2 q0 = sq[0], q1 = sq[1], q2 = sq[2], q3 = sq[3];
            vv[0] = u0.x + __ll2float_rn(q0.x) * INV232;
            vv[1] = u0.y + __ll2float_rn(q0.y) * INV232;
            vv[2] = u0.z + __ll2float_rn(q1.x) * INV232;
            vv[3] = u0.w + __ll2float_rn(q1.y) * INV232;
            vv[4] = u1.x + __ll2float_rn(q2.x) * INV232;
            vv[5] = u1.y + __ll2float_rn(q2.y) * INV232;
            vv[6] = u1.z + __ll2float_rn(q3.x) * INV232;
            vv[7] = u1.w + __ll2float_rn(q3.y) * INV232;
        }
        const int g  = tid >> 2;            // 32-float group (one per 4 threads)
        const int o0 = (tid & 3) * 8;       // offset within group
        float s = 0.f;
        #pragma unroll
        for (int q = 0; q < 8; q++) {
            vsh[g * GS + o0 + q] = vv[q];
            s += vv[q];
        }
        s += __shfl_down_sync(0xffffffffu, s, 2, 4);
        s += __shfl_down_sync(0xffffffffu, s, 1, 4);
        if ((tid & 3) == 0) seg[g] = s;
    }
    __syncthreads();

    // ---- 3. gated sum over this lane's two 32-float groups ------------------
    const float* base0 = vsh + woff * GS;          // group woff
    const float* base1 = vsh + (woff + 1) * GS;    // group woff+1
    int pc = __popc(ax) + __popc(ay);
    float sv;
    if (pc > 32) {
        sv = seg[woff] + seg[woff + 1];
        unsigned m;
        m = ~ax; while (m) { int b = __ffs((int)m) - 1; m &= m - 1; sv -= base0[b]; }
        m = ~ay; while (m) { int b = __ffs((int)m) - 1; m &= m - 1; sv -= base1[b]; }
    } else {
        sv = 0.f;
        unsigned m;
        m = ax; while (m) { int b = __ffs((int)m) - 1; m &= m - 1; sv += base0[b]; }
        m = ay; while (m) { int b = __ffs((int)m) - 1; m &= m - 1; sv += base1[b]; }
    }
    #pragma unroll
    for (int o = 16; o; o >>= 1) sv += __shfl_down_sync(0xffffffffu, sv, o);
    if (lane == 0) part[wid] = sv;
    __syncthreads();

    // ---- 4. combine halves + epilogue (threads 0..7 handle rows 0..7) ------
    if (tid < 8) {
        const int ii = blk * 8 + tid;
        float vi = vsh[(ii >> 5) * GS + (ii & 31)];
        float tot = part[2 * tid] + part[2 * tid + 1];
        if (!phase) {
            float s1 = __ll2float_rn(g_stepq[ii]) * INV232;
            float ns = s1 + 1.0986122886681098f * tot;            // ln 3
            g_step[ii] = ns;
            g_av2[ii]  = vi + ns;                                  // a1 + step
        } else {
            out_final[ii] = vi + g_step[ii] + 1.3862943611198906f * tot; // ln 4
        }
    }
}

// ---------------- mega: stepq scatter + barrier + hop0 + barrier + hop1 ------
__global__ __launch_bounds__(512, 4)
void mega_kernel(const void* __restrict__ ei, int ne, float* __restrict__ out) {
    __shared__ float vsh[128 * GS];
    __shared__ float seg[128];
    __shared__ float part[16];

    // ---- hop-1 scatter only (bitset + nbr lists built in kernel 1) ---------
    const int is64   = g_is64;
    const int stride = gridDim.x * blockDim.x;
    for (int e = blockIdx.x * blockDim.x + threadIdx.x; e < ne; e += stride) {
        int row, col;
        if (is64) {
            const long long* p = (const long long*)ei;
            row = (int)p[e];
            col = (int)p[ne + e];
        } else {
            const int* p = (const int*)ei;
            row = p[e];
            col = p[ne + e];
        }
        float v = 0.69314718055994531f * g_a0[col];
        long long q = __float2ll_rn(v * 4294967296.0f);
        atomicAdd((unsigned long long*)&g_stepq[row], (unsigned long long)q);
    }

    ticket_barrier(&g_tick[2], MEGA_B);
    hop_body(0, out, vsh, seg, part, blockIdx.x);
    ticket_barrier(&g_tick[3], MEGA_B);
    hop_body(1, out, vsh, seg, part, blockIdx.x);
}

// ---------------- launch ----------------------------------------------------
extern "C" void kernel_launch(void* const* d_in, const int* in_sizes, int n_in,
                              void* d_out, int out_size) {
    const float* coeffs = (const float*)d_in[0];
    const void*  ei     = d_in[1];
    const float* W0     = (const float*)d_in[2];
    const float* b0     = (const float*)d_in[3];
    const float* W1     = (const float*)d_in[4];
    const float* W2     = (const float*)d_in[5];
    const float* W3     = (const float*)d_in[6];
    const float* b3     = (const float*)d_in[7];
    float* out = (float*)d_out;

    const int ne = in_sizes[1] / 2;

    mlp_mega_kernel<<<256 + HLP_B, 128>>>(coeffs, W0, b0, W1, W2, W3, b3, ei, ne);

    mega_kernel<<<MEGA_B, 512>>>(ei, ne, out);
}